// round 1
// baseline (speedup 1.0000x reference)
#include <cuda_runtime.h>
#include <cuda_bf16.h>

// AdditiveDTMGP: 3-stage additive deep GP with Laplace-kernel features on a
// dyadic design u_i = i/64 (i=1..63), whitened by Rinv, reparameterized weights.
//
// Exact reformulation: exp(-|x-u|) splits at u<=x, so per (f,o) the 63-term
// kernel sum becomes  e^{-x}*A[f,o,j] + e^{x}*B[f,o,j]  with j = floor(64x)
// and prefix/suffix tables A,B built once per launch from the (input-constant)
// effective weights. Main kernel: half-warp per sample, lane = output channel.

#define MM 63

// Scratch tables (static device globals — no allocation).
__device__ float2 g_T1[32 * 64 * 16];   // [f][j][o] : (A, B)
__device__ float2 g_T2[16 * 64 * 16];   // [f][j][o]
__device__ float2 g_T3[64 * 16];        // [j][f]
__device__ float  g_bsum1[16];
__device__ float  g_bsum2[16];
__device__ float  g_bsum3;

// ---------------------------------------------------------------------------
// Table build: one block per feature-column (32 + 16 + 16 = 64 blocks).
// V[o][m] = sum_n Rinv[m][n] * (mu_w + softplus(rho_w)*eps_w)[o][n]
// A[j] = sum_{i<=j}  e^{u_i} V[i-1],  B[j] = sum_{i>j} e^{-u_i} V[i-1]
// ---------------------------------------------------------------------------
__global__ void build_tables(
    const float* __restrict__ U, const float* __restrict__ Rinv,
    const float* __restrict__ mw1, const float* __restrict__ rw1, const float* __restrict__ ew1,
    const float* __restrict__ mw2, const float* __restrict__ rw2, const float* __restrict__ ew2,
    const float* __restrict__ mw3, const float* __restrict__ rw3, const float* __restrict__ ew3)
{
    __shared__ float sR[MM * MM];
    __shared__ float sW[16 * MM];
    __shared__ float sV[16 * MM];
    __shared__ float sA[16 * 64];
    __shared__ float sEU[MM], sEMU[MM];

    const int blk = blockIdx.x, t = threadIdx.x;
    int stage, f, O;
    const float *mw, *rw, *ew;
    if (blk < 32)      { stage = 1; f = blk;      O = 16; mw = mw1; rw = rw1; ew = ew1; }
    else if (blk < 48) { stage = 2; f = blk - 32; O = 16; mw = mw2; rw = rw2; ew = ew2; }
    else               { stage = 3; f = blk - 48; O = 1;  mw = mw3; rw = rw3; ew = ew3; }

    for (int i = t; i < MM * MM; i += blockDim.x) sR[i] = Rinv[i];
    if (t < MM) { float u = U[t]; sEU[t] = __expf(u); sEMU[t] = __expf(-u); }
    for (int i = t; i < O * MM; i += blockDim.x) {
        int o = i / MM, n = i % MM;
        int gi = (f * O + o) * MM + n;
        float s = log1pf(__expf(rw[gi]));
        sW[i] = mw[gi] + s * ew[gi];
    }
    __syncthreads();

    for (int i = t; i < O * MM; i += blockDim.x) {
        int o = i / MM, m = i % MM;
        float v = 0.f;
        #pragma unroll 7
        for (int n = 0; n < MM; n++) v = fmaf(sR[m * MM + n], sW[o * MM + n], v);
        sV[i] = v;
    }
    __syncthreads();

    if (t < O) {
        const int o = t;
        float run = 0.f;
        sA[o * 64 + 0] = 0.f;
        for (int j = 1; j <= 63; j++) {
            run = fmaf(sEU[j - 1], sV[o * MM + j - 1], run);
            sA[o * 64 + j] = run;
        }
        float rb = 0.f;
        for (int j = 63; j >= 0; j--) {
            float2 val = make_float2(sA[o * 64 + j], rb);
            if (stage == 1)      g_T1[(f * 64 + j) * 16 + o] = val;
            else if (stage == 2) g_T2[(f * 64 + j) * 16 + o] = val;
            else                 g_T3[j * 16 + f] = val;
            if (j > 0) rb = fmaf(sEMU[j - 1], sV[o * MM + j - 1], rb);
        }
    }
}

// ---------------------------------------------------------------------------
// Bias sums + KL (single block, deterministic tree reduction).
// ---------------------------------------------------------------------------
__device__ __forceinline__ float kl_term(float mu, float rho) {
    float s = log1pf(__expf(rho));
    return fmaf(0.5f, fmaf(s, s, mu * mu), -logf(s)) - 0.5f;
}

__global__ void finalize_kernel(
    const float* __restrict__ mw1, const float* __restrict__ rw1,
    const float* __restrict__ mb1, const float* __restrict__ rb1, const float* __restrict__ eb1,
    const float* __restrict__ mw2, const float* __restrict__ rw2,
    const float* __restrict__ mb2, const float* __restrict__ rb2, const float* __restrict__ eb2,
    const float* __restrict__ mw3, const float* __restrict__ rw3,
    const float* __restrict__ mb3, const float* __restrict__ rb3, const float* __restrict__ eb3,
    float* __restrict__ out, int klIdx)
{
    const int t = threadIdx.x;

    // Bias sums: bsum[o] = sum_f (mu_b + softplus(rho_b)*eps_b)[f][o]
    if (t < 16) {
        float s = 0.f;
        for (int f = 0; f < 32; f++) {
            int i = f * 16 + t;
            s += mb1[i] + log1pf(__expf(rb1[i])) * eb1[i];
        }
        g_bsum1[t] = s;
    } else if (t < 32) {
        int o = t - 16;
        float s = 0.f;
        for (int f = 0; f < 16; f++) {
            int i = f * 16 + o;
            s += mb2[i] + log1pf(__expf(rb2[i])) * eb2[i];
        }
        g_bsum2[o] = s;
    } else if (t == 32) {
        float s = 0.f;
        for (int f = 0; f < 16; f++)
            s += mb3[f] + log1pf(__expf(rb3[f])) * eb3[f];
        g_bsum3 = s;
    }

    // KL over all (mu, rho) pairs of the 3 stages (w and b).
    float kl = 0.f;
    for (int i = t; i < 32 * 16 * MM; i += blockDim.x) kl += kl_term(mw1[i], rw1[i]);
    for (int i = t; i < 16 * 16 * MM; i += blockDim.x) kl += kl_term(mw2[i], rw2[i]);
    for (int i = t; i < 16 * MM;      i += blockDim.x) kl += kl_term(mw3[i], rw3[i]);
    for (int i = t; i < 32 * 16;      i += blockDim.x) kl += kl_term(mb1[i], rb1[i]);
    for (int i = t; i < 16 * 16;      i += blockDim.x) kl += kl_term(mb2[i], rb2[i]);
    for (int i = t; i < 16;           i += blockDim.x) kl += kl_term(mb3[i], rb3[i]);

    __shared__ float red[256];
    red[t] = kl;
    __syncthreads();
    for (int s = 128; s > 0; s >>= 1) {
        if (t < s) red[t] += red[t + s];
        __syncthreads();
    }
    if (t == 0) out[klIdx] = red[0];
}

// ---------------------------------------------------------------------------
// Forward: half-warp per sample, lane (o = lane&15) = output channel.
// Hidden activations stay in registers, broadcast via shfl.
// ---------------------------------------------------------------------------
__global__ void __launch_bounds__(256) fwd_kernel(
    const float* __restrict__ x, float* __restrict__ out, int nB)
{
    const int warp = threadIdx.x >> 5, lane = threadIdx.x & 31;
    const int sub = lane >> 4, o = lane & 15;
    const int b = blockIdx.x * 16 + warp * 2 + sub;
    if (b >= nB) return;  // half-warp granularity exit; masks below are per-half

    const unsigned mask = 0xFFFFu << (sub << 4);
    const int base = sub << 4;

    const float xv0 = x[b * 32 + o];
    const float xv1 = x[b * 32 + 16 + o];

    // ---- stage 1: D=32 features -> 16 hidden ----
    float acc = 0.f;
    #pragma unroll
    for (int f = 0; f < 32; f++) {
        float src = (f < 16) ? xv0 : xv1;
        float xs = __shfl_sync(mask, src, base | (f & 15));
        float ex  = __expf(xs);
        float emx = __expf(-xs);
        int j = (int)fminf(fmaxf(xs * 64.f, 0.f), 63.f);
        float2 tv = g_T1[(f * 64 + j) * 16 + o];
        acc = fmaf(emx, tv.x, fmaf(ex, tv.y, acc));
    }
    float h1 = acc + g_bsum1[o];

    // ---- stage 2: 16 -> 16 ----
    acc = 0.f;
    #pragma unroll
    for (int f = 0; f < 16; f++) {
        float xs = __shfl_sync(mask, h1, base | f);
        float ex  = __expf(xs);
        float emx = __expf(-xs);
        int j = (int)fminf(fmaxf(xs * 64.f, 0.f), 63.f);
        float2 tv = g_T2[(f * 64 + j) * 16 + o];
        acc = fmaf(emx, tv.x, fmaf(ex, tv.y, acc));
    }
    float h2 = acc + g_bsum2[o];

    // ---- stage 3: 16 -> 1 (lane o is feature o) ----
    {
        float xs = h2;
        float ex  = __expf(xs);
        float emx = __expf(-xs);
        int j = (int)fminf(fmaxf(xs * 64.f, 0.f), 63.f);
        float2 tv = g_T3[j * 16 + o];
        float c = fmaf(emx, tv.x, ex * tv.y);
        c += __shfl_xor_sync(mask, c, 8);
        c += __shfl_xor_sync(mask, c, 4);
        c += __shfl_xor_sync(mask, c, 2);
        c += __shfl_xor_sync(mask, c, 1);
        if (o == 0) out[b] = c + g_bsum3;
    }
}

// ---------------------------------------------------------------------------
extern "C" void kernel_launch(void* const* d_in, const int* in_sizes, int n_in,
                              void* d_out, int out_size)
{
    const float* x    = (const float*)d_in[0];
    const float* U    = (const float*)d_in[1];
    const float* Rinv = (const float*)d_in[2];

    const float* mw1 = (const float*)d_in[3];
    const float* rw1 = (const float*)d_in[4];
    const float* mb1 = (const float*)d_in[5];
    const float* rb1 = (const float*)d_in[6];
    const float* ew1 = (const float*)d_in[7];
    const float* eb1 = (const float*)d_in[8];

    const float* mw2 = (const float*)d_in[9];
    const float* rw2 = (const float*)d_in[10];
    const float* mb2 = (const float*)d_in[11];
    const float* rb2 = (const float*)d_in[12];
    const float* ew2 = (const float*)d_in[13];
    const float* eb2 = (const float*)d_in[14];

    const float* mw3 = (const float*)d_in[15];
    const float* rw3 = (const float*)d_in[16];
    const float* mb3 = (const float*)d_in[17];
    const float* rb3 = (const float*)d_in[18];
    const float* ew3 = (const float*)d_in[19];
    const float* eb3 = (const float*)d_in[20];

    const int nB = in_sizes[0] / 32;
    float* out = (float*)d_out;

    build_tables<<<64, 256>>>(U, Rinv, mw1, rw1, ew1, mw2, rw2, ew2, mw3, rw3, ew3);
    finalize_kernel<<<1, 256>>>(mw1, rw1, mb1, rb1, eb1,
                                mw2, rw2, mb2, rb2, eb2,
                                mw3, rw3, mb3, rb3, eb3,
                                out, out_size - 1);
    fwd_kernel<<<(nB + 15) / 16, 256>>>(x, out, nB);
}

// round 2
// speedup vs baseline: 1.9316x; 1.9316x over previous
#include <cuda_runtime.h>
#include <cuda_bf16.h>

// AdditiveDTMGP: 3-stage additive deep GP, Laplace kernel on dyadic design
// u_i = i/64 (i=1..63), whitened by Rinv (upper-triangular), reparam weights.
//
// Exact split: exp(-|x-u|) = e^{-x}e^{u} (u<=x) / e^{x}e^{-u} (u>x), so the
// 63-term sum per (f,o) collapses to a 2-term lookup at j = floor(64x).
// Stage 1 (x in [0,1)): tables premultiplied by e^{-+j/64}, stored as
// (P,Q)=(A~+B~, B~-A~); contribution = P(1+t^2/2) + Q t(1+t^2/6), t=x-j/64,
// |t|<1/64 -> poly exact to ~2e-9, ZERO MUFU. Stages 2/3: raw (A,B) + exp.

#define MM 63

__device__ float2 g_T1[32 * 64 * 16];   // stage1 [f][j][o] : (P, Q)
__device__ float2 g_T2[16 * 64 * 16];   // stage2 [f][j][o] : (A, B)
__device__ float2 g_T3[64 * 16];        // stage3 [j][f]    : (A, B)
__device__ float  g_bsum1[16];
__device__ float  g_bsum2[16];
__device__ float  g_bsum3;
__device__ float  g_klpart[65];

__device__ __forceinline__ float kl_term(float mu, float s) {
    return fmaf(0.5f, fmaf(s, s, mu * mu), -__logf(s)) - 0.5f;
}

// ---------------------------------------------------------------------------
// Prep kernel: 65 blocks.
//   blocks 0..63  : table build for one feature-column + KL partial (weights)
//   block  64     : bias sums + bias-KL partial
// ---------------------------------------------------------------------------
__global__ void build_tables(
    const float* __restrict__ U, const float* __restrict__ Rinv,
    const float* __restrict__ mw1, const float* __restrict__ rw1, const float* __restrict__ ew1,
    const float* __restrict__ mw2, const float* __restrict__ rw2, const float* __restrict__ ew2,
    const float* __restrict__ mw3, const float* __restrict__ rw3, const float* __restrict__ ew3,
    const float* __restrict__ mb1, const float* __restrict__ rb1, const float* __restrict__ eb1,
    const float* __restrict__ mb2, const float* __restrict__ rb2, const float* __restrict__ eb2,
    const float* __restrict__ mb3, const float* __restrict__ rb3, const float* __restrict__ eb3)
{
    const int blk = blockIdx.x, t = threadIdx.x;

    __shared__ float red[256];

    if (blk == 64) {
        // ---- bias sums + bias KL ----
        float kl = 0.f;
        for (int i = t; i < 32 * 16; i += blockDim.x) {
            float s = log1pf(__expf(rb1[i]));
            kl += kl_term(mb1[i], s);
        }
        for (int i = t; i < 16 * 16; i += blockDim.x) {
            float s = log1pf(__expf(rb2[i]));
            kl += kl_term(mb2[i], s);
        }
        for (int i = t; i < 16; i += blockDim.x) {
            float s = log1pf(__expf(rb3[i]));
            kl += kl_term(mb3[i], s);
        }
        if (t < 16) {
            float s = 0.f;
            for (int f = 0; f < 32; f++) {
                int i = f * 16 + t;
                s += mb1[i] + log1pf(__expf(rb1[i])) * eb1[i];
            }
            g_bsum1[t] = s;
        } else if (t < 32) {
            int o = t - 16;
            float s = 0.f;
            for (int f = 0; f < 16; f++) {
                int i = f * 16 + o;
                s += mb2[i] + log1pf(__expf(rb2[i])) * eb2[i];
            }
            g_bsum2[o] = s;
        } else if (t == 32) {
            float s = 0.f;
            for (int f = 0; f < 16; f++)
                s += mb3[f] + log1pf(__expf(rb3[f])) * eb3[f];
            g_bsum3 = s;
        }
        red[t] = kl;
        __syncthreads();
        for (int s = 128; s > 0; s >>= 1) {
            if (t < s) red[t] += red[t + s];
            __syncthreads();
        }
        if (t == 0) g_klpart[64] = red[0];
        return;
    }

    __shared__ float sR[MM * MM];
    __shared__ float sW[16 * MM];
    __shared__ float sV[16 * MM];
    __shared__ float sA[16 * 64];
    __shared__ float sEU[MM], sEMU[MM];
    __shared__ float sEJ[64], sEMJ[64];

    int stage, f, O;
    const float *mw, *rw, *ew;
    if (blk < 32)      { stage = 1; f = blk;      O = 16; mw = mw1; rw = rw1; ew = ew1; }
    else if (blk < 48) { stage = 2; f = blk - 32; O = 16; mw = mw2; rw = rw2; ew = ew2; }
    else               { stage = 3; f = blk - 48; O = 1;  mw = mw3; rw = rw3; ew = ew3; }

    for (int i = t; i < MM * MM; i += blockDim.x) sR[i] = Rinv[i];
    if (t < MM) { float u = U[t]; sEU[t] = __expf(u); sEMU[t] = __expf(-u); }
    if (t < 64) { float v = (float)t * 0.015625f; sEJ[t] = __expf(v); sEMJ[t] = __expf(-v); }

    float kl = 0.f;
    for (int i = t; i < O * MM; i += blockDim.x) {
        int o = i / MM, n = i % MM;
        int gi = (f * O + o) * MM + n;
        float mu = mw[gi];
        float s  = log1pf(__expf(rw[gi]));
        sW[i] = mu + s * ew[gi];
        kl += kl_term(mu, s);
    }
    red[t] = kl;
    __syncthreads();

    // V[o][m] = sum_{n>=m} Rinv[m][n] * W[o][n]   (Rinv upper-triangular)
    for (int i = t; i < O * MM; i += blockDim.x) {
        int o = i / MM, m = i % MM;
        float v = 0.f;
        for (int n = m; n < MM; n++) v = fmaf(sR[m * MM + n], sW[o * MM + n], v);
        sV[i] = v;
    }

    for (int s = 128; s > 0; s >>= 1) {
        if (t < s) red[t] += red[t + s];
        __syncthreads();
    }
    if (t == 0) g_klpart[blk] = red[0];

    if (t < O) {
        const int o = t;
        float run = 0.f;
        sA[o * 64 + 0] = 0.f;
        for (int j = 1; j <= 63; j++) {
            run = fmaf(sEU[j - 1], sV[o * MM + j - 1], run);
            sA[o * 64 + j] = run;
        }
        float rb = 0.f;   // B[j] suffix
        for (int j = 63; j >= 0; j--) {
            float A = sA[o * 64 + j], B = rb;
            if (stage == 1) {
                float At = A * sEMJ[j];     // A * e^{-j/64}
                float Bt = B * sEJ[j];      // B * e^{+j/64}
                g_T1[(f * 64 + j) * 16 + o] = make_float2(At + Bt, Bt - At);
            } else if (stage == 2) {
                g_T2[(f * 64 + j) * 16 + o] = make_float2(A, B);
            } else {
                g_T3[j * 16 + f] = make_float2(A, B);
            }
            if (j > 0) rb = fmaf(sEMU[j - 1], sV[o * MM + j - 1], rb);
        }
    }
}

// ---------------------------------------------------------------------------
// Forward: half-warp per sample, lane (o = lane&15) = output channel.
// ---------------------------------------------------------------------------
__global__ void __launch_bounds__(256) fwd_kernel(
    const float* __restrict__ x, float* __restrict__ out, int nB, int klIdx)
{
    // KL final sum: deterministic serial add by one thread, overlapped.
    if (blockIdx.x == 0 && threadIdx.x == 0) {
        float s = 0.f;
        #pragma unroll 1
        for (int i = 0; i < 65; i++) s += g_klpart[i];
        out[klIdx] = s;
    }

    const int warp = threadIdx.x >> 5, lane = threadIdx.x & 31;
    const int sub = lane >> 4, o = lane & 15;
    const int b = blockIdx.x * 16 + warp * 2 + sub;
    if (b >= nB) return;

    const unsigned mask = 0xFFFFu << (sub << 4);
    const int base = sub << 4;

    const float xv0 = x[b * 32 + o];
    const float xv1 = x[b * 32 + 16 + o];

    // ---- stage 1: 32 features, x in [0,1): MUFU-free polynomial path ----
    float acc = 0.f;
    #pragma unroll
    for (int f = 0; f < 32; f++) {
        float src = (f < 16) ? xv0 : xv1;
        float xs = __shfl_sync(mask, src, base | (f & 15));
        int j = (int)fminf(fmaxf(xs * 64.f, 0.f), 63.f);
        float tt = fmaf((float)j, -0.015625f, xs);   // t = x - j/64, 0<=t<1/64
        float t2 = tt * tt;
        float ca = fmaf(t2, 0.5f, 1.0f);                   // ~cosh(t)
        float st = tt * fmaf(t2, 0.16666667f, 1.0f);       // ~sinh(t)
        float2 pq = g_T1[(f * 64 + j) * 16 + o];
        acc = fmaf(pq.x, ca, fmaf(pq.y, st, acc));
    }
    float h1 = acc + g_bsum1[o];

    // ---- stage 2: 16 -> 16, exact exp path (h unbounded) ----
    acc = 0.f;
    #pragma unroll
    for (int f = 0; f < 16; f++) {
        float xs = __shfl_sync(mask, h1, base | f);
        float ex  = __expf(xs);
        float emx = __expf(-xs);
        int j = (int)fminf(fmaxf(xs * 64.f, 0.f), 63.f);
        float2 tv = g_T2[(f * 64 + j) * 16 + o];
        acc = fmaf(emx, tv.x, fmaf(ex, tv.y, acc));
    }
    float h2 = acc + g_bsum2[o];

    // ---- stage 3: 16 -> 1 (lane o is feature o) ----
    {
        float xs = h2;
        float ex  = __expf(xs);
        float emx = __expf(-xs);
        int j = (int)fminf(fmaxf(xs * 64.f, 0.f), 63.f);
        float2 tv = g_T3[j * 16 + o];
        float c = fmaf(emx, tv.x, ex * tv.y);
        c += __shfl_xor_sync(mask, c, 8);
        c += __shfl_xor_sync(mask, c, 4);
        c += __shfl_xor_sync(mask, c, 2);
        c += __shfl_xor_sync(mask, c, 1);
        if (o == 0) out[b] = c + g_bsum3;
    }
}

// ---------------------------------------------------------------------------
extern "C" void kernel_launch(void* const* d_in, const int* in_sizes, int n_in,
                              void* d_out, int out_size)
{
    const float* x    = (const float*)d_in[0];
    const float* U    = (const float*)d_in[1];
    const float* Rinv = (const float*)d_in[2];

    const float* mw1 = (const float*)d_in[3];
    const float* rw1 = (const float*)d_in[4];
    const float* mb1 = (const float*)d_in[5];
    const float* rb1 = (const float*)d_in[6];
    const float* ew1 = (const float*)d_in[7];
    const float* eb1 = (const float*)d_in[8];

    const float* mw2 = (const float*)d_in[9];
    const float* rw2 = (const float*)d_in[10];
    const float* mb2 = (const float*)d_in[11];
    const float* rb2 = (const float*)d_in[12];
    const float* ew2 = (const float*)d_in[13];
    const float* eb2 = (const float*)d_in[14];

    const float* mw3 = (const float*)d_in[15];
    const float* rw3 = (const float*)d_in[16];
    const float* mb3 = (const float*)d_in[17];
    const float* rb3 = (const float*)d_in[18];
    const float* ew3 = (const float*)d_in[19];
    const float* eb3 = (const float*)d_in[20];

    const int nB = in_sizes[0] / 32;
    float* out = (float*)d_out;

    build_tables<<<65, 256>>>(U, Rinv,
                              mw1, rw1, ew1, mw2, rw2, ew2, mw3, rw3, ew3,
                              mb1, rb1, eb1, mb2, rb2, eb2, mb3, rb3, eb3);
    fwd_kernel<<<(nB + 15) / 16, 256>>>(x, out, nB, out_size - 1);
}

// round 4
// speedup vs baseline: 3.2649x; 1.6903x over previous
#include <cuda_runtime.h>
#include <cuda_bf16.h>

// AdditiveDTMGP: 3-stage additive deep GP, Laplace kernel on dyadic design
// u_i = i/64 (i=1..63), whitened by Rinv (upper-triangular), reparam weights.
//
// Exact split: exp(-|x-u|) = e^{-x}e^{u} (u<=x) / e^{x}e^{-u} (u>x) collapses
// each 63-term sum to a 2-term table lookup at j = floor(64x). Stage 1 tables
// are premultiplied by e^{-+j/64} and stored as (P,Q); contribution =
// P*cosh(t)+Q*sinh(t) with t = x - j/64, |t| < 1/64 -> 2-term poly, no MUFU.
// Clamped j keeps stages 2/3 EXACT for any x (A[0]=0, B[63]=0).

#define MM 63

__device__ float2 g_T1[32 * 64 * 16];   // stage1 [f][j][o] : (P, Q)
__device__ float2 g_T2[16 * 64 * 16];   // stage2 [f][j][o] : (A, B)
__device__ float2 g_T3[64 * 16];        // stage3 [j][f]    : (A, B)
__device__ float  g_bsum1[16];
__device__ float  g_bsum2[16];
__device__ float  g_bsum3;
__device__ float  g_klpart[65];

__device__ __forceinline__ float kl_term(float mu, float s) {
    return fmaf(0.5f, fmaf(s, s, mu * mu), -__logf(s)) - 0.5f;
}

// ---------------------------------------------------------------------------
// Prep: 65 blocks. blocks 0..63 = one feature-column table + weight-KL part,
// block 64 = bias sums + bias-KL. All phases fully thread-parallel
// (no serial scans: A/B computed as predicated fixed-length sums).
// ---------------------------------------------------------------------------
__global__ void __launch_bounds__(256) build_tables(
    const float* __restrict__ U, const float* __restrict__ Rinv,
    const float* __restrict__ mw1, const float* __restrict__ rw1, const float* __restrict__ ew1,
    const float* __restrict__ mw2, const float* __restrict__ rw2, const float* __restrict__ ew2,
    const float* __restrict__ mw3, const float* __restrict__ rw3, const float* __restrict__ ew3,
    const float* __restrict__ mb1, const float* __restrict__ rb1, const float* __restrict__ eb1,
    const float* __restrict__ mb2, const float* __restrict__ rb2, const float* __restrict__ eb2,
    const float* __restrict__ mb3, const float* __restrict__ rb3, const float* __restrict__ eb3)
{
    const int blk = blockIdx.x, t = threadIdx.x;
    __shared__ float red[256];

    if (blk == 64) {
        float kl = 0.f;
        for (int i = t; i < 32 * 16; i += 256) kl += kl_term(mb1[i], log1pf(__expf(rb1[i])));
        for (int i = t; i < 16 * 16; i += 256) kl += kl_term(mb2[i], log1pf(__expf(rb2[i])));
        for (int i = t; i < 16;      i += 256) kl += kl_term(mb3[i], log1pf(__expf(rb3[i])));
        if (t < 16) {
            float s = 0.f;
            for (int f = 0; f < 32; f++) {
                int i = f * 16 + t;
                s += mb1[i] + log1pf(__expf(rb1[i])) * eb1[i];
            }
            g_bsum1[t] = s;
        } else if (t < 32) {
            int o = t - 16;
            float s = 0.f;
            for (int f = 0; f < 16; f++) {
                int i = f * 16 + o;
                s += mb2[i] + log1pf(__expf(rb2[i])) * eb2[i];
            }
            g_bsum2[o] = s;
        } else if (t == 32) {
            float s = 0.f;
            for (int f = 0; f < 16; f++)
                s += mb3[f] + log1pf(__expf(rb3[f])) * eb3[f];
            g_bsum3 = s;
        }
        red[t] = kl;
        __syncthreads();
        for (int s = 128; s > 0; s >>= 1) {
            if (t < s) red[t] += red[t + s];
            __syncthreads();
        }
        if (t == 0) g_klpart[64] = red[0];
        return;
    }

    __shared__ float sR[MM * MM];
    __shared__ float sW[16 * MM];
    __shared__ float sP[16 * 64];   // P[o][i] = e^{i/64} V[o][i-1], i=1..63
    __shared__ float sQ[16 * 64];   // Q[o][i] = e^{-i/64} V[o][i-1]
    __shared__ float sEJ[64], sEMJ[64];

    int stage, f, O;
    const float *mw, *rw, *ew;
    if (blk < 32)      { stage = 1; f = blk;      O = 16; mw = mw1; rw = rw1; ew = ew1; }
    else if (blk < 48) { stage = 2; f = blk - 32; O = 16; mw = mw2; rw = rw2; ew = ew2; }
    else               { stage = 3; f = blk - 48; O = 1;  mw = mw3; rw = rw3; ew = ew3; }

    #pragma unroll 4
    for (int i = t; i < MM * MM; i += 256) sR[i] = Rinv[i];
    if (t < 64) { float v = (float)t * 0.015625f; sEJ[t] = __expf(v); sEMJ[t] = __expf(-v); }

    // Phase A: effective weights + weight-KL partial
    float kl = 0.f;
    for (int i = t; i < O * MM; i += 256) {
        float mu = mw[(f * O) * MM + i];
        float s  = log1pf(__expf(rw[(f * O) * MM + i]));
        sW[i] = mu + s * ew[(f * O) * MM + i];
        kl += kl_term(mu, s);
    }
    red[t] = kl;
    __syncthreads();

    // Phase B: V[o][m] = sum_n Rinv[m][n] * W[o][n] (full fixed loop; lower
    // triangle of Rinv is zero), then P/Q premultiplied, stored at [o][m+1].
    for (int i = t; i < O * MM; i += 256) {
        int o = i / MM, m = i % MM;
        const float* r = &sR[m * MM];
        const float* w = &sW[o * MM];
        float v = 0.f;
        #pragma unroll
        for (int n = 0; n < MM; n++) v = fmaf(r[n], w[n], v);
        sP[o * 64 + (m + 1)] = v * sEJ[m + 1];
        sQ[o * 64 + (m + 1)] = v * sEMJ[m + 1];
    }
    if (t < O) { sP[t * 64] = 0.f; sQ[t * 64] = 0.f; }
    __syncthreads();

    // KL reduction (overlaps with nothing critical; cheap)
    for (int s = 128; s > 0; s >>= 1) {
        if (t < s) red[t] += red[t + s];
        __syncthreads();
    }
    if (t == 0) g_klpart[blk] = red[0];

    // Phase C: per (o,j) entry, A = sum_{i<=j} P[i], B = sum_{i>j} Q[i].
    // Fixed 63-iteration predicated loop; LDS reads are warp-broadcast.
    for (int e = t; e < O * 64; e += 256) {
        int o = e >> 6, j = e & 63;
        const float* p = &sP[o * 64];
        const float* q = &sQ[o * 64];
        float A = 0.f, B = 0.f;
        #pragma unroll
        for (int i = 1; i <= 63; i++) {
            float pv = p[i], qv = q[i];
            A += (i <= j) ? pv : 0.f;
            B += (i >  j) ? qv : 0.f;
        }
        if (stage == 1) {
            float At = A * sEMJ[j];
            float Bt = B * sEJ[j];
            g_T1[(f * 64 + j) * 16 + o] = make_float2(At + Bt, Bt - At);
        } else if (stage == 2) {
            g_T2[(f * 64 + j) * 16 + o] = make_float2(A, B);
        } else {
            g_T3[j * 16 + f] = make_float2(A, B);
        }
    }
}

// ---------------------------------------------------------------------------
// Forward: half-warp per sample, lane (o = lane&15) = output channel.
// ---------------------------------------------------------------------------
__global__ void __launch_bounds__(256) fwd_kernel(
    const float* __restrict__ x, float* __restrict__ out, int nB, int klIdx)
{
    if (blockIdx.x == 0 && threadIdx.x == 0) {
        float s = 0.f;
        #pragma unroll 1
        for (int i = 0; i < 65; i++) s += g_klpart[i];
        out[klIdx] = s;
    }

    const int warp = threadIdx.x >> 5, lane = threadIdx.x & 31;
    const int sub = lane >> 4, o = lane & 15;
    const int b = blockIdx.x * 16 + warp * 2 + sub;
    if (b >= nB) return;

    const unsigned mask = 0xFFFFu << (sub << 4);
    const int base = sub << 4;

    const float xv0 = __ldg(&x[b * 32 + o]);
    const float xv1 = __ldg(&x[b * 32 + 16 + o]);
    const float bs1 = __ldg(&g_bsum1[o]);
    const float bs2 = __ldg(&g_bsum2[o]);

    // ---- stage 1: 32 features, MUFU-free table+poly path ----
    float acc = 0.f;
    #pragma unroll
    for (int f = 0; f < 32; f++) {
        float src = (f < 16) ? xv0 : xv1;
        float xs = __shfl_sync(mask, src, base | (f & 15));
        int j = (int)fminf(fmaxf(xs * 64.f, 0.f), 63.f);
        float tt = fmaf((float)j, -0.015625f, xs);
        float t2 = tt * tt;
        float ca = fmaf(t2, 0.5f, 1.0f);
        float st = tt * fmaf(t2, 0.16666667f, 1.0f);
        float2 pq = __ldg(&g_T1[(f * 64 + j) * 16 + o]);
        acc = fmaf(pq.x, ca, fmaf(pq.y, st, acc));
    }
    float h1 = acc + bs1;

    // ---- stage 2: 16 -> 16, exact exp path ----
    acc = 0.f;
    #pragma unroll
    for (int f = 0; f < 16; f++) {
        float xs = __shfl_sync(mask, h1, base | f);
        float ex  = __expf(xs);
        float emx = __expf(-xs);
        int j = (int)fminf(fmaxf(xs * 64.f, 0.f), 63.f);
        float2 tv = __ldg(&g_T2[(f * 64 + j) * 16 + o]);
        acc = fmaf(emx, tv.x, fmaf(ex, tv.y, acc));
    }
    float h2 = acc + bs2;

    // ---- stage 3: 16 -> 1 ----
    {
        float xs = h2;
        float ex  = __expf(xs);
        float emx = __expf(-xs);
        int j = (int)fminf(fmaxf(xs * 64.f, 0.f), 63.f);
        float2 tv = __ldg(&g_T3[j * 16 + o]);
        float c = fmaf(emx, tv.x, ex * tv.y);
        c += __shfl_xor_sync(mask, c, 8);
        c += __shfl_xor_sync(mask, c, 4);
        c += __shfl_xor_sync(mask, c, 2);
        c += __shfl_xor_sync(mask, c, 1);
        if (o == 0) out[b] = c + __ldg(&g_bsum3);
    }
}

// ---------------------------------------------------------------------------
extern "C" void kernel_launch(void* const* d_in, const int* in_sizes, int n_in,
                              void* d_out, int out_size)
{
    const float* x    = (const float*)d_in[0];
    const float* U    = (const float*)d_in[1];
    const float* Rinv = (const float*)d_in[2];

    const float* mw1 = (const float*)d_in[3];
    const float* rw1 = (const float*)d_in[4];
    const float* mb1 = (const float*)d_in[5];
    const float* rb1 = (const float*)d_in[6];
    const float* ew1 = (const float*)d_in[7];
    const float* eb1 = (const float*)d_in[8];

    const float* mw2 = (const float*)d_in[9];
    const float* rw2 = (const float*)d_in[10];
    const float* mb2 = (const float*)d_in[11];
    const float* rb2 = (const float*)d_in[12];
    const float* ew2 = (const float*)d_in[13];
    const float* eb2 = (const float*)d_in[14];

    const float* mw3 = (const float*)d_in[15];
    const float* rw3 = (const float*)d_in[16];
    const float* mb3 = (const float*)d_in[17];
    const float* rb3 = (const float*)d_in[18];
    const float* ew3 = (const float*)d_in[19];
    const float* eb3 = (const float*)d_in[20];

    const int nB = in_sizes[0] / 32;
    float* out = (float*)d_out;

    build_tables<<<65, 256>>>(U, Rinv,
                              mw1, rw1, ew1, mw2, rw2, ew2, mw3, rw3, ew3,
                              mb1, rb1, eb1, mb2, rb2, eb2, mb3, rb3, eb3);
    fwd_kernel<<<(nB + 15) / 16, 256>>>(x, out, nB, out_size - 1);
}

// round 5
// speedup vs baseline: 3.6257x; 1.1105x over previous
#include <cuda_runtime.h>
#include <cuda_bf16.h>

// AdditiveDTMGP: 3-stage additive deep GP, Laplace kernel on dyadic design
// u_i = i/64 (i=1..63), whitened by Rinv (upper-triangular), reparam weights.
//
// Exact split: exp(-|x-u|) = e^{-x}e^{u} (u<=x) / e^{x}e^{-u} (u>x) collapses
// each 63-term sum to a 2-term table lookup at j = floor(64x). Stage 1 tables
// premultiplied by e^{-+j/64}, stored (P,Q); contribution = P*cosh t + Q*sinh t,
// t = x - j/64 in [0,1/64) -> 2-term poly, no MUFU. Stages 2/3 exact (A,B)+exp.
//
// fwd: half-warp per sample, lane = output channel. Per-f nonlinearities are
// computed ONCE by the owning lane, broadcast via per-warp SMEM float4 slots
// (LDS.128 broadcast), so the inner loop is LDS + LDG + 2 FMA only.

#define MM 63

__device__ float2 g_T1[32 * 64 * 16];   // stage1 [f][j][o] : (P, Q)
__device__ float2 g_T2[16 * 64 * 16];   // stage2 [f][j][o] : (A, B)
__device__ float2 g_T3[64 * 16];        // stage3 [j][f]    : (A, B)
__device__ float  g_bsum1[16];
__device__ float  g_bsum2[16];
__device__ float  g_bsum3;
__device__ float  g_klpart[65];

__device__ __forceinline__ float kl_term(float mu, float s) {
    return fmaf(0.5f, fmaf(s, s, mu * mu), -__logf(s)) - 0.5f;
}

// ---------------------------------------------------------------------------
// Prep: 65 blocks. blocks 0..63 = one feature-column table + weight-KL part,
// block 64 = bias sums + bias-KL. Fully thread-parallel.
// ---------------------------------------------------------------------------
__global__ void __launch_bounds__(256) build_tables(
    const float* __restrict__ U, const float* __restrict__ Rinv,
    const float* __restrict__ mw1, const float* __restrict__ rw1, const float* __restrict__ ew1,
    const float* __restrict__ mw2, const float* __restrict__ rw2, const float* __restrict__ ew2,
    const float* __restrict__ mw3, const float* __restrict__ rw3, const float* __restrict__ ew3,
    const float* __restrict__ mb1, const float* __restrict__ rb1, const float* __restrict__ eb1,
    const float* __restrict__ mb2, const float* __restrict__ rb2, const float* __restrict__ eb2,
    const float* __restrict__ mb3, const float* __restrict__ rb3, const float* __restrict__ eb3)
{
    const int blk = blockIdx.x, t = threadIdx.x;
    __shared__ float red[256];

    if (blk == 64) {
        float kl = 0.f;
        for (int i = t; i < 32 * 16; i += 256) kl += kl_term(mb1[i], log1pf(__expf(rb1[i])));
        for (int i = t; i < 16 * 16; i += 256) kl += kl_term(mb2[i], log1pf(__expf(rb2[i])));
        for (int i = t; i < 16;      i += 256) kl += kl_term(mb3[i], log1pf(__expf(rb3[i])));
        if (t < 16) {
            float s = 0.f;
            for (int f = 0; f < 32; f++) {
                int i = f * 16 + t;
                s += mb1[i] + log1pf(__expf(rb1[i])) * eb1[i];
            }
            g_bsum1[t] = s;
        } else if (t < 32) {
            int o = t - 16;
            float s = 0.f;
            for (int f = 0; f < 16; f++) {
                int i = f * 16 + o;
                s += mb2[i] + log1pf(__expf(rb2[i])) * eb2[i];
            }
            g_bsum2[o] = s;
        } else if (t == 32) {
            float s = 0.f;
            for (int f = 0; f < 16; f++)
                s += mb3[f] + log1pf(__expf(rb3[f])) * eb3[f];
            g_bsum3 = s;
        }
        red[t] = kl;
        __syncthreads();
        for (int s = 128; s > 0; s >>= 1) {
            if (t < s) red[t] += red[t + s];
            __syncthreads();
        }
        if (t == 0) g_klpart[64] = red[0];
        return;
    }

    __shared__ float sR[64 * MM];   // padded: row m=63 is scratch (never stored)
    __shared__ float sW[16 * MM];
    __shared__ float sP[16 * 64];   // P[o][i] = e^{i/64} V[o][i-1], i=1..63
    __shared__ float sQ[16 * 64];
    __shared__ float sEJ[64], sEMJ[64];

    int stage, f, O;
    const float *mw, *rw, *ew;
    if (blk < 32)      { stage = 1; f = blk;      O = 16; mw = mw1; rw = rw1; ew = ew1; }
    else if (blk < 48) { stage = 2; f = blk - 32; O = 16; mw = mw2; rw = rw2; ew = ew2; }
    else               { stage = 3; f = blk - 48; O = 1;  mw = mw3; rw = rw3; ew = ew3; }

    #pragma unroll 4
    for (int i = t; i < MM * MM; i += 256) sR[i] = Rinv[i];
    if (t < 64) { float v = (float)t * 0.015625f; sEJ[t] = __expf(v); sEMJ[t] = __expf(-v); }

    float kl = 0.f;
    for (int i = t; i < O * MM; i += 256) {
        float mu = mw[(f * O) * MM + i];
        float s  = log1pf(__expf(rw[(f * O) * MM + i]));
        sW[i] = mu + s * ew[(f * O) * MM + i];
        kl += kl_term(mu, s);
    }
    red[t] = kl;
    __syncthreads();

    // Phase B: 4 consecutive m of one o per thread (w[n] shared across them).
    {
        int e4 = t * 4;
        if (e4 < O * 64) {
            int o = e4 >> 6, m0 = e4 & 63;
            const float* w = &sW[o * MM];
            const float* r0 = &sR[(m0 + 0) * MM];
            const float* r1 = &sR[(m0 + 1) * MM];
            const float* r2 = &sR[(m0 + 2) * MM];
            const float* r3 = &sR[(m0 + 3) * MM];
            float v0 = 0.f, v1 = 0.f, v2 = 0.f, v3 = 0.f;
            #pragma unroll
            for (int n = 0; n < MM; n++) {
                float wn = w[n];
                v0 = fmaf(r0[n], wn, v0);
                v1 = fmaf(r1[n], wn, v1);
                v2 = fmaf(r2[n], wn, v2);
                v3 = fmaf(r3[n], wn, v3);
            }
            float vv[4] = {v0, v1, v2, v3};
            #pragma unroll
            for (int k = 0; k < 4; k++) {
                int m = m0 + k;
                if (m < MM) {
                    sP[o * 64 + (m + 1)] = vv[k] * sEJ[m + 1];
                    sQ[o * 64 + (m + 1)] = vv[k] * sEMJ[m + 1];
                }
            }
        }
        if (t < O) { sP[t * 64] = 0.f; sQ[t * 64] = 0.f; }
    }
    __syncthreads();

    for (int s = 128; s > 0; s >>= 1) {
        if (t < s) red[t] += red[t + s];
        __syncthreads();
    }
    if (t == 0) g_klpart[blk] = red[0];

    // Phase C: A = sum_{i<=j} P[i], B = sum_{i>j} Q[i], predicated fixed loop.
    for (int e = t; e < O * 64; e += 256) {
        int o = e >> 6, j = e & 63;
        const float* p = &sP[o * 64];
        const float* q = &sQ[o * 64];
        float A = 0.f, B = 0.f;
        #pragma unroll
        for (int i = 1; i <= 63; i++) {
            A += (i <= j) ? p[i] : 0.f;
            B += (i >  j) ? q[i] : 0.f;
        }
        if (stage == 1) {
            float At = A * sEMJ[j];
            float Bt = B * sEJ[j];
            g_T1[(f * 64 + j) * 16 + o] = make_float2(At + Bt, Bt - At);
        } else if (stage == 2) {
            g_T2[(f * 64 + j) * 16 + o] = make_float2(A, B);
        } else {
            g_T3[j * 16 + f] = make_float2(A, B);
        }
    }
}

// ---------------------------------------------------------------------------
// Forward. Per-warp SMEM float4 slots broadcast precomputed nonlinearities.
// ---------------------------------------------------------------------------
__global__ void __launch_bounds__(256) fwd_kernel(
    const float* __restrict__ x, float* __restrict__ out, int nB, int klIdx)
{
    __shared__ float4 sT[8][64];   // [warp][sub*32 + f]

    if (blockIdx.x == 0 && threadIdx.x == 0) {
        float s = 0.f;
        #pragma unroll 1
        for (int i = 0; i < 65; i++) s += g_klpart[i];
        out[klIdx] = s;
    }

    const int warp = threadIdx.x >> 5, lane = threadIdx.x & 31;
    const int sub = lane >> 4, o = lane & 15;
    const int b = blockIdx.x * 16 + warp * 2 + sub;
    const int bc = (b < nB) ? b : (nB - 1);
    const unsigned mask = 0xFFFFu << (sub << 4);

    float4* tw = &sT[warp][sub * 32];

    const float xv0 = __ldg(&x[bc * 32 + o]);
    const float xv1 = __ldg(&x[bc * 32 + 16 + o]);
    const float bs1 = __ldg(&g_bsum1[o]);
    const float bs2 = __ldg(&g_bsum2[o]);
    const float bs3 = __ldg(&g_bsum3);

    // ---- stage 1 precompute: own (cosh t, sinh t, j*128) for xv0, xv1 ----
    {
        float j0f = fminf(fmaxf(xv0 * 64.f, 0.f), 63.f);
        int   j0  = (int)j0f;
        float t0  = fmaf((float)j0, -0.015625f, xv0);
        float t02 = t0 * t0;
        tw[o] = make_float4(fmaf(t02, 0.5f, 1.f),
                            t0 * fmaf(t02, 0.16666667f, 1.f),
                            __int_as_float(j0 * 128), 0.f);
        float j1f = fminf(fmaxf(xv1 * 64.f, 0.f), 63.f);
        int   j1  = (int)j1f;
        float t1  = fmaf((float)j1, -0.015625f, xv1);
        float t12 = t1 * t1;
        tw[16 + o] = make_float4(fmaf(t12, 0.5f, 1.f),
                                 t1 * fmaf(t12, 0.16666667f, 1.f),
                                 __int_as_float(j1 * 128), 0.f);
    }
    __syncwarp();

    const char* base1 = (const char*)g_T1 + o * 8;
    float acc = 0.f;
    #pragma unroll
    for (int f = 0; f < 32; f++) {
        float4 tr = tw[f];
        const float2 pq = *(const float2*)(base1 + f * 8192 + __float_as_int(tr.z));
        acc = fmaf(pq.x, tr.x, fmaf(pq.y, tr.y, acc));
    }
    float h1 = acc + bs1;
    __syncwarp();

    // ---- stage 2 precompute: own (e^{-h}, e^{h}, j*128) ----
    {
        float ex  = __expf(h1);
        float emx = __expf(-h1);
        int j = (int)fminf(fmaxf(h1 * 64.f, 0.f), 63.f);
        tw[o] = make_float4(emx, ex, __int_as_float(j * 128), 0.f);
    }
    __syncwarp();

    const char* base2 = (const char*)g_T2 + o * 8;
    acc = 0.f;
    #pragma unroll
    for (int f = 0; f < 16; f++) {
        float4 tr = tw[f];
        const float2 ab = *(const float2*)(base2 + f * 8192 + __float_as_int(tr.z));
        acc = fmaf(tr.x, ab.x, fmaf(tr.y, ab.y, acc));
    }
    float h2 = acc + bs2;

    // ---- stage 3: 16 -> 1 (lane o is feature o) ----
    {
        float ex  = __expf(h2);
        float emx = __expf(-h2);
        int j = (int)fminf(fmaxf(h2 * 64.f, 0.f), 63.f);
        float2 tv = __ldg(&g_T3[j * 16 + o]);
        float c = fmaf(emx, tv.x, ex * tv.y);
        c += __shfl_xor_sync(mask, c, 8);
        c += __shfl_xor_sync(mask, c, 4);
        c += __shfl_xor_sync(mask, c, 2);
        c += __shfl_xor_sync(mask, c, 1);
        if (o == 0 && b < nB) out[b] = c + bs3;
    }
}

// ---------------------------------------------------------------------------
extern "C" void kernel_launch(void* const* d_in, const int* in_sizes, int n_in,
                              void* d_out, int out_size)
{
    const float* x    = (const float*)d_in[0];
    const float* U    = (const float*)d_in[1];
    const float* Rinv = (const float*)d_in[2];

    const float* mw1 = (const float*)d_in[3];
    const float* rw1 = (const float*)d_in[4];
    const float* mb1 = (const float*)d_in[5];
    const float* rb1 = (const float*)d_in[6];
    const float* ew1 = (const float*)d_in[7];
    const float* eb1 = (const float*)d_in[8];

    const float* mw2 = (const float*)d_in[9];
    const float* rw2 = (const float*)d_in[10];
    const float* mb2 = (const float*)d_in[11];
    const float* rb2 = (const float*)d_in[12];
    const float* ew2 = (const float*)d_in[13];
    const float* eb2 = (const float*)d_in[14];

    const float* mw3 = (const float*)d_in[15];
    const float* rw3 = (const float*)d_in[16];
    const float* mb3 = (const float*)d_in[17];
    const float* rb3 = (const float*)d_in[18];
    const float* ew3 = (const float*)d_in[19];
    const float* eb3 = (const float*)d_in[20];

    const int nB = in_sizes[0] / 32;
    float* out = (float*)d_out;

    build_tables<<<65, 256>>>(U, Rinv,
                              mw1, rw1, ew1, mw2, rw2, ew2, mw3, rw3, ew3,
                              mb1, rb1, eb1, mb2, rb2, eb2, mb3, rb3, eb3);
    fwd_kernel<<<(nB + 15) / 16, 256>>>(x, out, nB, out_size - 1);
}